// round 11
// baseline (speedup 1.0000x reference)
#include <cuda_runtime.h>

#define LOG2E 1.4426950408889634f
#define NI 12                 // intervals per attention
#define NNODE 9               // Chebyshev nodes per interval (degree 8)
#define NODES (NI * NNODE)    // 108

#define NBLK 132              // grid size; <= SM count -> all blocks co-resident
#define NTHR 512

#define PROJ_KC 24            // 768 / 32
#define PROJ_KCH 32
#define MLP_KC 120            // 3840 / 32
#define MLP_KCH 32

// phase B units: 192 node units (32 b x 6 grp, 18 nodes each) + 72 proj units
#define B_NODE_UNITS 192
#define B_UNITS (B_NODE_UNITS + PROJ_KC * 3)   // 264 = 2 * NBLK

// ---------------- scratch (__device__ globals; allocation-free rule) -------
__device__ float  g_fused[32 * 2304];            // [sentence | scene | speaker]
__device__ float  g_h_part[MLP_KC * 32 * 256];   // mlp1 partials [kc][b][j]
__device__ float  g_pp[3 * PROJ_KC * 32 * 512];  // proj partials [task][kc][b][j]
__device__ float2 g_nodes[32 * NODES];           // fused node table [b][m]
__device__ float  g_frange[32 * 2];              // fused range [b][min,max]
__device__ unsigned g_cnt = 0;                   // barrier arrivals (self-resetting)
__device__ unsigned g_gen = 0;                   // barrier generation (monotonic)

__constant__ float CHEB[9] = {1.f, 0.92387953f, 0.70710678f, 0.38268343f, 0.f,
                              -0.38268343f, -0.70710678f, -0.92387953f, -1.f};
__constant__ float LAMB[9] = {0.5f, -1.f, 1.f, -1.f, 1.f, -1.f, 1.f, -1.f, 0.5f};

__device__ __forceinline__ float ex2f(float x) {
    float y; asm("ex2.approx.f32 %0, %1;" : "=f"(y) : "f"(x)); return y;
}
__device__ __forceinline__ float wredsum(float v) {
#pragma unroll
    for (int o = 16; o > 0; o >>= 1) v += __shfl_xor_sync(0xffffffffu, v, o);
    return v;
}

// Canonical grid barrier (CG-style): all NBLK blocks co-resident by design.
__device__ __forceinline__ void grid_barrier() {
    __syncthreads();
    if (threadIdx.x == 0) {
        __threadfence();
        unsigned g = *(volatile unsigned*)&g_gen;
        if (atomicAdd(&g_cnt, 1u) == NBLK - 1) {
            g_cnt = 0;
            __threadfence();
            atomicAdd(&g_gen, 1u);
        } else {
            while (*(volatile unsigned*)&g_gen == g) { __nanosleep(32); }
        }
        __threadfence();
    }
    __syncthreads();
}

__device__ __forceinline__ float interp_s(float x, float xmin, float w, float hw,
                                          float invw,
                                          const float* __restrict__ snum,
                                          const float* __restrict__ sden) {
    int c = (int)((x - xmin) * invw);
    c = (c < 0) ? 0 : ((c >= NI) ? NI - 1 : c);
    const float x0 = xmin + (c + 0.5f) * w;
    const int base = c * NNODE;
    float wn = 0.f, wd = 0.f, hitn = 0.f, hitd = 1.f;
    bool hit = false;
#pragma unroll
    for (int m = 0; m < NNODE; m++) {
        float d = x - (x0 + hw * CHEB[m]);
        if (fabsf(d) < 1e-10f) { hit = true; hitn = snum[base + m]; hitd = sden[base + m]; d = 1.f; }
        float wm = __fdividef(LAMB[m], d);
        wn = fmaf(wm, snum[base + m], wn);
        wd = fmaf(wm, sden[base + m], wd);
    }
    return hit ? __fdividef(hitn, hitd) : __fdividef(wn, wd);
}

__device__ __forceinline__ float interp_g(float x, float xmin, float w, float hw,
                                          float invw,
                                          const float2* __restrict__ nodes) {
    int c = (int)((x - xmin) * invw);
    c = (c < 0) ? 0 : ((c >= NI) ? NI - 1 : c);
    const float x0 = xmin + (c + 0.5f) * w;
    const float2* nb = nodes + c * NNODE;
    float wn = 0.f, wd = 0.f, hitn = 0.f, hitd = 1.f;
    bool hit = false;
#pragma unroll
    for (int m = 0; m < NNODE; m++) {
        float2 nd = nb[m];
        float d = x - (x0 + hw * CHEB[m]);
        if (fabsf(d) < 1e-10f) { hit = true; hitn = nd.x; hitd = nd.y; d = 1.f; }
        float wm = __fdividef(LAMB[m], d);
        wn = fmaf(wm, nd.x, wn);
        wd = fmaf(wm, nd.y, wd);
    }
    return hit ? __fdividef(hitn, hitd) : __fdividef(wn, wd);
}

// ---------------------------------------------------------------------------
// THE kernel: all four phases, 3 software grid barriers, 1 launch.
// ---------------------------------------------------------------------------
__global__ void __launch_bounds__(NTHR) monolith(const float* __restrict__ sent,
                                                 const float* __restrict__ ts,
                                                 const float* __restrict__ oth,
                                                 const float* __restrict__ sd,
                                                 const float* __restrict__ ss,
                                                 const float* __restrict__ Wsh,
                                                 const float* __restrict__ bsh,
                                                 const float* __restrict__ W1,
                                                 const float* __restrict__ b1,
                                                 const float* __restrict__ W2,
                                                 const float* __restrict__ b2,
                                                 float* __restrict__ out) {
    const int bid = blockIdx.x;
    const int tid = threadIdx.x, lane = tid & 31, wid = tid >> 5;

    __shared__ __align__(16) union SM {
        struct { float sq[768], sk[768], sv[768], snum[NODES], sden[NODES], red[32]; } a;
        struct { float sf[2304], red[32]; } bn;
        struct { float xs[PROJ_KCH][36]; } bp;
        struct { float xs[2][MLP_KCH][36]; } c;
        struct { float sred[2][256], h[256]; } d;
    } sm;

    // ================= Phase A: pre attentions + sentence copy ==============
    // units [0,64): heavy (b, task); units [64,96): copy b.
    for (int u = bid; u < 96; u += NBLK) {
        if (u >= 64) {
            int b = u - 64;
            for (int i = tid; i < 768; i += NTHR) g_fused[b * 2304 + i] = sent[b * 768 + i];
            continue;
        }
        const int b = u & 31, task = u >> 5;          // 0 or 1
        const float* q = (task == 0) ? oth : ss;
        const float* k = (task == 0) ? ts  : ss;
        const float* v = (task == 0) ? ts  : sd;
        const int outoff = (task == 0) ? 1536 : 768;

        for (int i = tid; i < 768; i += NTHR) {
            sm.a.sq[i] = q[b * 768 + i];
            sm.a.sk[i] = k[b * 768 + i];
            sm.a.sv[i] = v[b * 768 + i];
        }
        __syncthreads();

        float lmin = 1e30f, lmax = -1e30f;
        for (int i = tid; i < 768; i += NTHR) {
            float x = sm.a.sq[i];
            lmin = fminf(lmin, x); lmax = fmaxf(lmax, x);
        }
#pragma unroll
        for (int o = 16; o > 0; o >>= 1) {
            lmin = fminf(lmin, __shfl_xor_sync(0xffffffffu, lmin, o));
            lmax = fmaxf(lmax, __shfl_xor_sync(0xffffffffu, lmax, o));
        }
        if (lane == 0) { sm.a.red[wid] = lmin; sm.a.red[16 + wid] = lmax; }
        __syncthreads();
        float xmin = sm.a.red[0], xmax = sm.a.red[16];
#pragma unroll
        for (int i = 1; i < 16; i++) {
            xmin = fminf(xmin, sm.a.red[i]);
            xmax = fmaxf(xmax, sm.a.red[16 + i]);
        }

        const float w  = (xmax - xmin) * (1.f / NI);
        const float hw = 0.5f * w;

        for (int m = wid; m < NODES; m += 16) {
            const int c = m / NNODE, mm = m - c * NNODE;
            const float Xl = (xmin + (c + 0.5f) * w + hw * CHEB[mm]) * LOG2E;
            float sn = 0.f, sd_ = 0.f;
            for (int t = lane; t < 768; t += 32) {
                float e = ex2f(Xl * sm.a.sk[t]);
                sd_ += e;
                sn = fmaf(e, sm.a.sv[t], sn);
            }
            sn = wredsum(sn); sd_ = wredsum(sd_);
            if (lane == 0) { sm.a.snum[m] = sn; sm.a.sden[m] = sd_; }
        }
        __syncthreads();

        const float invw = __fdividef(1.f, w);
        for (int s = tid; s < 768; s += NTHR)
            g_fused[b * 2304 + outoff + s] =
                interp_s(sm.a.sq[s], xmin, w, hw, invw, sm.a.snum, sm.a.sden);
        __syncthreads();
    }

    grid_barrier();

    // ================= Phase B: fused node table + projections ==============
    for (int u = bid; u < B_UNITS; u += NBLK) {
        if (u < B_NODE_UNITS) {
            const int b = u & 31, grp = u >> 5;       // grp 0..5, 18 nodes each
            for (int i = tid; i < 576; i += NTHR)
                *reinterpret_cast<float4*>(sm.bn.sf + i * 4) =
                    *reinterpret_cast<const float4*>(g_fused + b * 2304 + i * 4);
            __syncthreads();

            float lmin = 1e30f, lmax = -1e30f;
            for (int i = tid; i < 2304; i += NTHR) {
                float x = sm.bn.sf[i];
                lmin = fminf(lmin, x); lmax = fmaxf(lmax, x);
            }
#pragma unroll
            for (int o = 16; o > 0; o >>= 1) {
                lmin = fminf(lmin, __shfl_xor_sync(0xffffffffu, lmin, o));
                lmax = fmaxf(lmax, __shfl_xor_sync(0xffffffffu, lmax, o));
            }
            if (lane == 0) { sm.bn.red[wid] = lmin; sm.bn.red[16 + wid] = lmax; }
            __syncthreads();
            float xmin = sm.bn.red[0], xmax = sm.bn.red[16];
#pragma unroll
            for (int i = 1; i < 16; i++) {
                xmin = fminf(xmin, sm.bn.red[i]);
                xmax = fmaxf(xmax, sm.bn.red[16 + i]);
            }

            if (grp == 0 && tid == 0) { g_frange[b * 2] = xmin; g_frange[b * 2 + 1] = xmax; }

            const float w  = (xmax - xmin) * (1.f / NI);
            const float hw = 0.5f * w;
            const int m0 = grp * 18;

            for (int m = m0 + wid; m < m0 + 18; m += 16) {
                const int c = m / NNODE, mm = m - c * NNODE;
                const float Xl = (xmin + (c + 0.5f) * w + hw * CHEB[mm]) * LOG2E;
                float sn = 0.f, sd_ = 0.f;
                for (int t = lane; t < 2304; t += 32) {
                    float f = sm.bn.sf[t];
                    float e = ex2f(Xl * f);
                    sd_ += e;
                    sn = fmaf(e, f, sn);              // v == f
                }
                sn = wredsum(sn); sd_ = wredsum(sd_);
                if (lane == 0) g_nodes[b * NODES + m] = make_float2(sn, sd_);
            }
        } else {
            const int p    = u - B_NODE_UNITS;        // 0..71
            const int task = p / PROJ_KC;
            const int kc   = p - task * PROJ_KC;
            const int j    = tid;                     // 0..511
            const int i0   = kc * PROJ_KCH;

            for (int e = tid; e < PROJ_KCH * 32; e += NTHR) {
                int i = e & 31, b = e >> 5;
                sm.bp.xs[i][b] = (task == 0) ? sent[b * 768 + i0 + i]
                                             : g_fused[b * 2304 + 768 * task + i0 + i];
            }
            __syncthreads();

            float acc[32];
#pragma unroll
            for (int b = 0; b < 32; b++) acc[b] = 0.f;
#pragma unroll
            for (int i = 0; i < PROJ_KCH; i++) {
                float wv = Wsh[(i0 + i) * 512 + j];
#pragma unroll
                for (int b4 = 0; b4 < 8; b4++) {
                    float4 x = *reinterpret_cast<const float4*>(&sm.bp.xs[i][b4 * 4]);
                    acc[b4 * 4 + 0] = fmaf(x.x, wv, acc[b4 * 4 + 0]);
                    acc[b4 * 4 + 1] = fmaf(x.y, wv, acc[b4 * 4 + 1]);
                    acc[b4 * 4 + 2] = fmaf(x.z, wv, acc[b4 * 4 + 2]);
                    acc[b4 * 4 + 3] = fmaf(x.w, wv, acc[b4 * 4 + 3]);
                }
            }
#pragma unroll
            for (int b = 0; b < 32; b++)
                g_pp[(((size_t)task * PROJ_KC + kc) * 32 + b) * 512 + j] = acc[b];
        }
        __syncthreads();
    }

    grid_barrier();

    // ================= Phase C: mlp1 (fused assemble), 2 kc per unit ========
    for (int u = bid; u < MLP_KC / 2; u += NBLK) {
        const int sub = tid >> 8;                     // 0,1
        const int j   = tid & 255;
        const int kc  = u * 2 + sub;
        const int i0  = kc * MLP_KCH;

        if (kc < 72) {
            for (int e = j; e < MLP_KCH * 32; e += 256) {
                int ii = e & 31, b = e >> 5;
                const float xmin = g_frange[b * 2], xmax = g_frange[b * 2 + 1];
                const float w  = (xmax - xmin) * (1.f / NI);
                const float hw = 0.5f * w;
                const float invw = __fdividef(1.f, w);
                const float x = g_fused[b * 2304 + i0 + ii];
                sm.c.xs[sub][ii][b] = interp_g(x, xmin, w, hw, invw, g_nodes + b * NODES);
            }
        } else {
            const int t0   = i0 - 2304;
            const int task = t0 >> 9;
            const int jj0  = t0 & 511;
            for (int e = j; e < MLP_KCH * 32; e += 256) {
                int jl = e & 31, b = e >> 5;
                const int jj = jj0 + jl;
                float a = bsh[jj];
                const float* pp = g_pp + (((size_t)task * PROJ_KC) * 32 + b) * 512 + jj;
#pragma unroll
                for (int s = 0; s < PROJ_KC; s++) a += pp[(size_t)s * 32 * 512];
                sm.c.xs[sub][jl][b] = a;
            }
        }
        __syncthreads();

        float acc[32];
#pragma unroll
        for (int b = 0; b < 32; b++) acc[b] = 0.f;
#pragma unroll
        for (int i = 0; i < MLP_KCH; i++) {
            float w = W1[(i0 + i) * 256 + j];
#pragma unroll
            for (int b4 = 0; b4 < 8; b4++) {
                float4 x = *reinterpret_cast<const float4*>(&sm.c.xs[sub][i][b4 * 4]);
                acc[b4 * 4 + 0] = fmaf(x.x, w, acc[b4 * 4 + 0]);
                acc[b4 * 4 + 1] = fmaf(x.y, w, acc[b4 * 4 + 1]);
                acc[b4 * 4 + 2] = fmaf(x.z, w, acc[b4 * 4 + 2]);
                acc[b4 * 4 + 3] = fmaf(x.w, w, acc[b4 * 4 + 3]);
            }
        }
#pragma unroll
        for (int b = 0; b < 32; b++)
            g_h_part[((size_t)kc * 32 + b) * 256 + j] = acc[b];
        __syncthreads();
    }

    grid_barrier();

    // ================= Phase D: tail (reduce + relu + mlp2 + sigmoid) =======
    for (int u = bid; u < 32; u += NBLK) {
        const int b  = u;
        const int j  = tid & 255;
        const int qt = tid >> 8;                      // 0,1 -> 60 kcs each

        const float* src = g_h_part + ((size_t)(qt * 60) * 32 + b) * 256 + j;
        float a0 = 0.f, a1 = 0.f, a2 = 0.f, a3 = 0.f, a4 = 0.f, a5 = 0.f;
#pragma unroll
        for (int i = 0; i < 60; i += 6) {
            a0 += src[(size_t)(i + 0) * 32 * 256];
            a1 += src[(size_t)(i + 1) * 32 * 256];
            a2 += src[(size_t)(i + 2) * 32 * 256];
            a3 += src[(size_t)(i + 3) * 32 * 256];
            a4 += src[(size_t)(i + 4) * 32 * 256];
            a5 += src[(size_t)(i + 5) * 32 * 256];
        }
        sm.d.sred[qt][j] = ((a0 + a1) + (a2 + a3)) + (a4 + a5);
        __syncthreads();

        if (qt == 0) {
            float v = (sm.d.sred[0][j] + sm.d.sred[1][j]) + b1[j];
            sm.d.h[j] = fmaxf(v, 0.f);
        }
        __syncthreads();

        if (wid < 7) {
            float s = 0.f;
#pragma unroll
            for (int q = 0; q < 8; q++)
                s = fmaf(sm.d.h[q * 32 + lane], W2[(q * 32 + lane) * 7 + wid], s);
#pragma unroll
            for (int o = 16; o > 0; o >>= 1) s += __shfl_xor_sync(0xffffffffu, s, o);
            if (lane == 0) out[b * 7 + wid] = 1.f / (1.f + __expf(-(s + b2[wid])));
        }
        __syncthreads();
    }
}

extern "C" void kernel_launch(void* const* d_in, const int* in_sizes, int n_in,
                              void* d_out, int out_size) {
    const float* sent = (const float*)d_in[0];
    const float* ts   = (const float*)d_in[1];
    const float* oth  = (const float*)d_in[2];
    const float* sd   = (const float*)d_in[3];
    const float* ss   = (const float*)d_in[4];
    const float* Wsh  = (const float*)d_in[5];
    const float* bsh  = (const float*)d_in[6];
    const float* W1   = (const float*)d_in[7];
    const float* b1   = (const float*)d_in[8];
    const float* W2   = (const float*)d_in[9];
    const float* b2   = (const float*)d_in[10];
    float* out = (float*)d_out;

    monolith<<<NBLK, NTHR>>>(sent, ts, oth, sd, ss, Wsh, bsh, W1, b1, W2, b2, out);
}

// round 12
// speedup vs baseline: 1.0520x; 1.0520x over previous
#include <cuda_runtime.h>

#define LOG2E 1.4426950408889634f
#define NI 12                 // intervals
#define NNODE 8               // Chebyshev-Lobatto nodes per interval (degree 7)
#define NODES (NI * NNODE)    // 96 = 3 rounds of 32 lanes

#define PROJ_KC 24            // 768 / 32
#define PROJ_KCH 32
#define MLP_KC 120            // 3840 / 32
#define MLP_KCH 32

// ---------------- scratch (__device__ globals; allocation-free rule) -------
__device__ float  g_fused[32 * 2304];            // [sentence | scene | speaker]
__device__ float  g_h_part[MLP_KC * 32 * 256];   // mlp1 partials [kc][b][j]
__device__ float  g_pp[3 * PROJ_KC * 32 * 512];  // proj partials [task][kc][b][j]
__device__ float2 g_nhalf[2][32 * 96];           // fused node tables (t-halves)
__device__ float  g_prange[32][3][2];            // piece ranges [b][piece][min,max]

__constant__ float CHEB[8] = {1.f, 0.90096887f, 0.62348980f, 0.22252093f,
                              -0.22252093f, -0.62348980f, -0.90096887f, -1.f};
__constant__ float LAMB[8] = {0.5f, -1.f, 1.f, -1.f, 1.f, -1.f, 1.f, -0.5f};

__device__ __forceinline__ float ex2f(float x) {
    float y; asm("ex2.approx.f32 %0, %1;" : "=f"(y) : "f"(x)); return y;
}

// 8-node barycentric eval from shared tables.
__device__ __forceinline__ float interp_s8(float x, float xmin, float w, float hw,
                                           float invw,
                                           const float* __restrict__ snum,
                                           const float* __restrict__ sden) {
    int c = (int)((x - xmin) * invw);
    c = (c < 0) ? 0 : ((c >= NI) ? NI - 1 : c);
    const float x0 = xmin + (c + 0.5f) * w;
    const int base = c * NNODE;
    float wn = 0.f, wd = 0.f, hitn = 0.f, hitd = 1.f;
    bool hit = false;
#pragma unroll
    for (int m = 0; m < NNODE; m++) {
        float d = x - (x0 + hw * CHEB[m]);
        if (fabsf(d) < 1e-10f) { hit = true; hitn = snum[base + m]; hitd = sden[base + m]; d = 1.f; }
        float wm = __fdividef(LAMB[m], d);
        wn = fmaf(wm, snum[base + m], wn);
        wd = fmaf(wm, sden[base + m], wd);
    }
    return hit ? __fdividef(hitn, hitd) : __fdividef(wn, wd);
}

// 8-node barycentric eval summing the two half-tables (deterministic A+B).
__device__ __forceinline__ float interp_g8(float x, float xmin, float w, float hw,
                                           float invw,
                                           const float2* __restrict__ nA,
                                           const float2* __restrict__ nB) {
    int c = (int)((x - xmin) * invw);
    c = (c < 0) ? 0 : ((c >= NI) ? NI - 1 : c);
    const float x0 = xmin + (c + 0.5f) * w;
    const int base = c * NNODE;
    float wn = 0.f, wd = 0.f, hitn = 0.f, hitd = 1.f;
    bool hit = false;
#pragma unroll
    for (int m = 0; m < NNODE; m++) {
        float2 a = nA[base + m], bb = nB[base + m];
        float nx = a.x + bb.x, ny = a.y + bb.y;
        float d = x - (x0 + hw * CHEB[m]);
        if (fabsf(d) < 1e-10f) { hit = true; hitn = nx; hitd = ny; d = 1.f; }
        float wm = __fdividef(LAMB[m], d);
        wn = fmaf(wm, nx, wn);
        wd = fmaf(wm, ny, wd);
    }
    return hit ? __fdividef(hitn, hitd) : __fdividef(wn, wd);
}

// ---------------------------------------------------------------------------
// Kernel 1: grid 120 x 512.
// bx<64: heavy pre-attention (b, task) — lane-per-node eval, NO shuffles.
// 64<=bx<96: sentence copy + range.   bx>=96: proj task 0 (reads only sent).
// ---------------------------------------------------------------------------
__global__ void __launch_bounds__(512) pre_kernel(const float* __restrict__ sent,
                                                  const float* __restrict__ ts,
                                                  const float* __restrict__ oth,
                                                  const float* __restrict__ sd,
                                                  const float* __restrict__ ss,
                                                  const float* __restrict__ Wsh) {
    const int bx = blockIdx.x;
    const int tid = threadIdx.x, lane = tid & 31, wid = tid >> 5;

    __shared__ __align__(16) union SM {
        struct {
            float sq[768], sk[768], sv[768];
            float spn[3][16][32], spd[3][16][32];
            float snum[NODES], sden[NODES];
            float red[32];
        } h;
        struct { float xs[PROJ_KCH][36]; } p;
    } sm;

    if (bx >= 96) {                       // ---- proj task 0 ----
        const int kc = bx - 96, i0 = kc * PROJ_KCH, j = tid;
        for (int e = tid; e < PROJ_KCH * 32; e += 512) {
            int i = e & 31, b = e >> 5;
            sm.p.xs[i][b] = sent[b * 768 + i0 + i];
        }
        __syncthreads();
        float acc[32];
#pragma unroll
        for (int b = 0; b < 32; b++) acc[b] = 0.f;
#pragma unroll
        for (int i = 0; i < PROJ_KCH; i++) {
            float wv = Wsh[(i0 + i) * 512 + j];
#pragma unroll
            for (int b4 = 0; b4 < 8; b4++) {
                float4 x = *reinterpret_cast<const float4*>(&sm.p.xs[i][b4 * 4]);
                acc[b4 * 4 + 0] = fmaf(x.x, wv, acc[b4 * 4 + 0]);
                acc[b4 * 4 + 1] = fmaf(x.y, wv, acc[b4 * 4 + 1]);
                acc[b4 * 4 + 2] = fmaf(x.z, wv, acc[b4 * 4 + 2]);
                acc[b4 * 4 + 3] = fmaf(x.w, wv, acc[b4 * 4 + 3]);
            }
        }
#pragma unroll
        for (int b = 0; b < 32; b++)
            g_pp[((size_t)kc * 32 + b) * 512 + j] = acc[b];
        return;
    }

    if (bx >= 64) {                       // ---- sentence copy + range ----
        const int b = bx - 64;
        float lmin = 1e30f, lmax = -1e30f;
        for (int i = tid; i < 768; i += 512) {
            float x = sent[b * 768 + i];
            g_fused[b * 2304 + i] = x;
            lmin = fminf(lmin, x); lmax = fmaxf(lmax, x);
        }
#pragma unroll
        for (int o = 16; o > 0; o >>= 1) {
            lmin = fminf(lmin, __shfl_xor_sync(0xffffffffu, lmin, o));
            lmax = fmaxf(lmax, __shfl_xor_sync(0xffffffffu, lmax, o));
        }
        if (lane == 0) { sm.h.red[wid] = lmin; sm.h.red[16 + wid] = lmax; }
        __syncthreads();
        if (tid == 0) {
            float mn = sm.h.red[0], mx = sm.h.red[16];
#pragma unroll
            for (int i = 1; i < 16; i++) {
                mn = fminf(mn, sm.h.red[i]); mx = fmaxf(mx, sm.h.red[16 + i]);
            }
            g_prange[b][0][0] = mn; g_prange[b][0][1] = mx;
        }
        return;
    }

    // ---- heavy pre-attention ----
    const int b = bx & 31, task = bx >> 5;
    const float* q = (task == 0) ? oth : ss;
    const float* k = (task == 0) ? ts  : ss;
    const float* v = (task == 0) ? ts  : sd;
    const int outoff = (task == 0) ? 1536 : 768;
    const int piece  = (task == 0) ? 2 : 1;

    for (int i = tid; i < 768; i += 512) {
        sm.h.sq[i] = q[b * 768 + i];
        sm.h.sk[i] = k[b * 768 + i];
        sm.h.sv[i] = v[b * 768 + i];
    }
    __syncthreads();

    float lmin = 1e30f, lmax = -1e30f;
    for (int i = tid; i < 768; i += 512) {
        float x = sm.h.sq[i];
        lmin = fminf(lmin, x); lmax = fmaxf(lmax, x);
    }
#pragma unroll
    for (int o = 16; o > 0; o >>= 1) {
        lmin = fminf(lmin, __shfl_xor_sync(0xffffffffu, lmin, o));
        lmax = fmaxf(lmax, __shfl_xor_sync(0xffffffffu, lmax, o));
    }
    if (lane == 0) { sm.h.red[wid] = lmin; sm.h.red[16 + wid] = lmax; }
    __syncthreads();
    float xmin = sm.h.red[0], xmax = sm.h.red[16];
#pragma unroll
    for (int i = 1; i < 16; i++) {
        xmin = fminf(xmin, sm.h.red[i]); xmax = fmaxf(xmax, sm.h.red[16 + i]);
    }

    const float w  = (xmax - xmin) * (1.f / NI);
    const float hw = 0.5f * w;

    // lane-per-node: lane owns node r*32+lane (3 rounds); warp owns t-chunk.
    float xl[3];
#pragma unroll
    for (int r = 0; r < 3; r++) {
        int m = r * 32 + lane, c = m >> 3, mm = m & 7;
        xl[r] = (xmin + (c + 0.5f) * w + hw * CHEB[mm]) * LOG2E;
    }
    float nm0 = 0.f, dn0 = 0.f, nm1 = 0.f, dn1 = 0.f, nm2 = 0.f, dn2 = 0.f;
    const int t0 = wid * 48;
#pragma unroll 4
    for (int tt = 0; tt < 48; tt++) {
        float f = sm.h.sk[t0 + tt];
        float vv = sm.h.sv[t0 + tt];
        float e0 = ex2f(xl[0] * f); dn0 += e0; nm0 = fmaf(e0, vv, nm0);
        float e1 = ex2f(xl[1] * f); dn1 += e1; nm1 = fmaf(e1, vv, nm1);
        float e2 = ex2f(xl[2] * f); dn2 += e2; nm2 = fmaf(e2, vv, nm2);
    }
    sm.h.spn[0][wid][lane] = nm0; sm.h.spd[0][wid][lane] = dn0;
    sm.h.spn[1][wid][lane] = nm1; sm.h.spd[1][wid][lane] = dn1;
    sm.h.spn[2][wid][lane] = nm2; sm.h.spd[2][wid][lane] = dn2;
    __syncthreads();

    if (tid < 192) {
        const int m = (tid < 96) ? tid : tid - 96;
        const int r = m >> 5, ln = m & 31;
        const float* src = (tid < 96) ? &sm.h.spn[r][0][ln] : &sm.h.spd[r][0][ln];
        float s = 0.f;
#pragma unroll
        for (int ww = 0; ww < 16; ww++) s += src[ww * 32];
        if (tid < 96) sm.h.snum[m] = s; else sm.h.sden[m] = s;
    }
    __syncthreads();

    const float invw = __fdividef(1.f, w);
    float omin = 1e30f, omax = -1e30f;
    for (int s = tid; s < 768; s += 512) {
        float val = interp_s8(sm.h.sq[s], xmin, w, hw, invw, sm.h.snum, sm.h.sden);
        g_fused[b * 2304 + outoff + s] = val;
        omin = fminf(omin, val); omax = fmaxf(omax, val);
    }
#pragma unroll
    for (int o = 16; o > 0; o >>= 1) {
        omin = fminf(omin, __shfl_xor_sync(0xffffffffu, omin, o));
        omax = fmaxf(omax, __shfl_xor_sync(0xffffffffu, omax, o));
    }
    __syncthreads();
    if (lane == 0) { sm.h.red[wid] = omin; sm.h.red[16 + wid] = omax; }
    __syncthreads();
    if (tid == 0) {
        float mn = sm.h.red[0], mx = sm.h.red[16];
#pragma unroll
        for (int i = 1; i < 16; i++) {
            mn = fminf(mn, sm.h.red[i]); mx = fmaxf(mx, sm.h.red[16 + i]);
        }
        g_prange[b][piece][0] = mn; g_prange[b][piece][1] = mx;
    }
}

// ---------------------------------------------------------------------------
// Kernel 2: grid 240 x 512.
// bx<192: fused node eval — (b, node-round r, t-half); lane-per-node.
// bx>=192: proj tasks 1,2 (48 blocks).
// ---------------------------------------------------------------------------
__global__ void __launch_bounds__(512) fat_kernel(const float* __restrict__ Wsh) {
    const int bx = blockIdx.x;
    const int tid = threadIdx.x, lane = tid & 31, wid = tid >> 5;

    __shared__ __align__(16) union SM {
        struct { float sf[1152]; float2 sp[16][32]; float bc[2]; } n;
        struct { float xs[PROJ_KCH][36]; } p;
    } sm;

    if (bx < 192) {
        const int b = bx & 31, q6 = bx >> 5;
        const int r = q6 % 3, half = q6 / 3;

        if (tid == 0) {
            float mn = fminf(fminf(g_prange[b][0][0], g_prange[b][1][0]), g_prange[b][2][0]);
            float mx = fmaxf(fmaxf(g_prange[b][0][1], g_prange[b][1][1]), g_prange[b][2][1]);
            sm.n.bc[0] = mn; sm.n.bc[1] = mx;
        }
        if (tid < 288)
            *reinterpret_cast<float4*>(sm.n.sf + tid * 4) =
                *reinterpret_cast<const float4*>(g_fused + b * 2304 + half * 1152 + tid * 4);
        __syncthreads();

        const float xmin = sm.n.bc[0], xmax = sm.n.bc[1];
        const float w  = (xmax - xmin) * (1.f / NI);
        const float hw = 0.5f * w;

        const int m = r * 32 + lane, c = m >> 3, mm = m & 7;
        const float xl = (xmin + (c + 0.5f) * w + hw * CHEB[mm]) * LOG2E;

        float nm = 0.f, dn = 0.f;
        const int t0 = wid * 72;
#pragma unroll 4
        for (int tt = 0; tt < 72; tt++) {
            float f = sm.n.sf[t0 + tt];
            float e = ex2f(xl * f);
            dn += e;
            nm = fmaf(e, f, nm);       // v == f
        }
        sm.n.sp[wid][lane] = make_float2(nm, dn);
        __syncthreads();

        if (tid < 32) {
            float sx = 0.f, sy = 0.f;
#pragma unroll
            for (int ww = 0; ww < 16; ww++) {
                float2 p = sm.n.sp[ww][tid];
                sx += p.x; sy += p.y;
            }
            g_nhalf[half][b * 96 + r * 32 + tid] = make_float2(sx, sy);
        }
        return;
    }

    // ----- proj tasks 1, 2 -----
    const int p    = bx - 192;
    const int task = 1 + p / PROJ_KC;
    const int kc   = p % PROJ_KC;
    const int j    = tid;
    const int i0   = kc * PROJ_KCH;

    for (int e = tid; e < PROJ_KCH * 32; e += 512) {
        int i = e & 31, b = e >> 5;
        sm.p.xs[i][b] = g_fused[b * 2304 + 768 * task + i0 + i];
    }
    __syncthreads();

    float acc[32];
#pragma unroll
    for (int b = 0; b < 32; b++) acc[b] = 0.f;
#pragma unroll
    for (int i = 0; i < PROJ_KCH; i++) {
        float wv = Wsh[(i0 + i) * 512 + j];
#pragma unroll
        for (int b4 = 0; b4 < 8; b4++) {
            float4 x = *reinterpret_cast<const float4*>(&sm.p.xs[i][b4 * 4]);
            acc[b4 * 4 + 0] = fmaf(x.x, wv, acc[b4 * 4 + 0]);
            acc[b4 * 4 + 1] = fmaf(x.y, wv, acc[b4 * 4 + 1]);
            acc[b4 * 4 + 2] = fmaf(x.z, wv, acc[b4 * 4 + 2]);
            acc[b4 * 4 + 3] = fmaf(x.w, wv, acc[b4 * 4 + 3]);
        }
    }
#pragma unroll
    for (int b = 0; b < 32; b++)
        g_pp[(((size_t)task * PROJ_KC + kc) * 32 + b) * 512 + j] = acc[b];
}

// ---------------------------------------------------------------------------
// Kernel 3: mlp1, grid 60 x 512 (2 kc per block).
// ---------------------------------------------------------------------------
__global__ void __launch_bounds__(512) mlp1_fused(const float* __restrict__ W1,
                                                  const float* __restrict__ bsh) {
    const int sub = threadIdx.x >> 8;          // 0,1
    const int j   = threadIdx.x & 255;
    const int kc  = blockIdx.x * 2 + sub;
    const int i0  = kc * MLP_KCH;

    __shared__ __align__(16) float xs[2][MLP_KCH][36];
    __shared__ float rxmin[32], rxmax[32];

    if (threadIdx.x < 32) {
        int b = threadIdx.x;
        rxmin[b] = fminf(fminf(g_prange[b][0][0], g_prange[b][1][0]), g_prange[b][2][0]);
        rxmax[b] = fmaxf(fmaxf(g_prange[b][0][1], g_prange[b][1][1]), g_prange[b][2][1]);
    }
    __syncthreads();

    if (kc < 72) {
        for (int e = j; e < MLP_KCH * 32; e += 256) {
            int ii = e & 31, b = e >> 5;
            const float xmin = rxmin[b], xmax = rxmax[b];
            const float w  = (xmax - xmin) * (1.f / NI);
            const float hw = 0.5f * w;
            const float invw = __fdividef(1.f, w);
            const float x = g_fused[b * 2304 + i0 + ii];
            xs[sub][ii][b] = interp_g8(x, xmin, w, hw, invw,
                                       g_nhalf[0] + b * 96, g_nhalf[1] + b * 96);
        }
    } else {
        const int t0   = i0 - 2304;
        const int task = t0 >> 9;
        const int jj0  = t0 & 511;
        for (int e = j; e < MLP_KCH * 32; e += 256) {
            int jl = e & 31, b = e >> 5;
            const int jj = jj0 + jl;
            float a = bsh[jj];
            const float* pp = g_pp + (((size_t)task * PROJ_KC) * 32 + b) * 512 + jj;
#pragma unroll
            for (int s = 0; s < PROJ_KC; s++) a += pp[(size_t)s * 32 * 512];
            xs[sub][jl][b] = a;
        }
    }
    __syncthreads();

    float acc[32];
#pragma unroll
    for (int b = 0; b < 32; b++) acc[b] = 0.f;
#pragma unroll
    for (int i = 0; i < MLP_KCH; i++) {
        float w = W1[(i0 + i) * 256 + j];
#pragma unroll
        for (int b4 = 0; b4 < 8; b4++) {
            float4 x = *reinterpret_cast<const float4*>(&xs[sub][i][b4 * 4]);
            acc[b4 * 4 + 0] = fmaf(x.x, w, acc[b4 * 4 + 0]);
            acc[b4 * 4 + 1] = fmaf(x.y, w, acc[b4 * 4 + 1]);
            acc[b4 * 4 + 2] = fmaf(x.z, w, acc[b4 * 4 + 2]);
            acc[b4 * 4 + 3] = fmaf(x.w, w, acc[b4 * 4 + 3]);
        }
    }
#pragma unroll
    for (int b = 0; b < 32; b++)
        g_h_part[((size_t)kc * 32 + b) * 256 + j] = acc[b];
}

// ---------------------------------------------------------------------------
// Kernel 4: tail — reduce + bias + relu + mlp2 + sigmoid. grid 32 x 1024.
// ---------------------------------------------------------------------------
__global__ void __launch_bounds__(1024) mlp_tail(const float* __restrict__ b1,
                                                 const float* __restrict__ W2,
                                                 const float* __restrict__ b2,
                                                 float* __restrict__ out) {
    const int b = blockIdx.x;
    const int j = threadIdx.x & 255;
    const int qt = threadIdx.x >> 8;          // 0..3, 30 kcs each
    const int w = threadIdx.x >> 5, lane = threadIdx.x & 31;

    __shared__ float sred[4][256];
    __shared__ float h[256];

    const float* src = g_h_part + ((size_t)(qt * 30) * 32 + b) * 256 + j;
    float a0 = 0.f, a1 = 0.f, a2 = 0.f, a3 = 0.f, a4 = 0.f, a5 = 0.f;
#pragma unroll
    for (int i = 0; i < 30; i += 6) {
        a0 += src[(size_t)(i + 0) * 32 * 256];
        a1 += src[(size_t)(i + 1) * 32 * 256];
        a2 += src[(size_t)(i + 2) * 32 * 256];
        a3 += src[(size_t)(i + 3) * 32 * 256];
        a4 += src[(size_t)(i + 4) * 32 * 256];
        a5 += src[(size_t)(i + 5) * 32 * 256];
    }
    sred[qt][j] = ((a0 + a1) + (a2 + a3)) + (a4 + a5);
    __syncthreads();

    if (qt == 0) {
        float v = ((sred[0][j] + sred[1][j]) + (sred[2][j] + sred[3][j])) + b1[j];
        h[j] = fmaxf(v, 0.f);
    }
    __syncthreads();

    if (w < 7) {
        float s = 0.f;
#pragma unroll
        for (int q = 0; q < 8; q++)
            s = fmaf(h[q * 32 + lane], W2[(q * 32 + lane) * 7 + w], s);
#pragma unroll
        for (int o = 16; o > 0; o >>= 1) s += __shfl_xor_sync(0xffffffffu, s, o);
        if (lane == 0) out[b * 7 + w] = 1.f / (1.f + __expf(-(s + b2[w])));
    }
}

extern "C" void kernel_launch(void* const* d_in, const int* in_sizes, int n_in,
                              void* d_out, int out_size) {
    const float* sent = (const float*)d_in[0];
    const float* ts   = (const float*)d_in[1];
    const float* oth  = (const float*)d_in[2];
    const float* sd   = (const float*)d_in[3];
    const float* ss   = (const float*)d_in[4];
    const float* Wsh  = (const float*)d_in[5];
    const float* bsh  = (const float*)d_in[6];
    const float* W1   = (const float*)d_in[7];
    const float* b1   = (const float*)d_in[8];
    const float* W2   = (const float*)d_in[9];
    const float* b2   = (const float*)d_in[10];
    float* out = (float*)d_out;

    pre_kernel<<<120, 512>>>(sent, ts, oth, sd, ss, Wsh);
    fat_kernel<<<240, 512>>>(Wsh);
    mlp1_fused<<<60, 512>>>(W1, bsh);
    mlp_tail<<<32, 1024>>>(b1, W2, b2, out);
}

// round 13
// speedup vs baseline: 1.2751x; 1.2120x over previous
#include <cuda_runtime.h>

#define LOG2E 1.4426950408889634f
#define NI 12                 // intervals per attention
#define NNODE 9               // Chebyshev nodes per interval (degree 8)
#define NODES (NI * NNODE)    // 108
#define NGRP 6                // node-groups for fused node eval (18 nodes each)

#define PROJ_KC 24            // 768 / 32
#define PROJ_KCH 32
#define MLP_KC 120            // 3840 / 32
#define MLP_KCH 32

#define FAT_NODE_BLOCKS (NGRP * 32)            // 192
#define FAT_PROJ_BLOCKS (PROJ_KC * 2 * 3)      // 144

// ---------------- scratch (__device__ globals; allocation-free rule) -------
__device__ float  g_fused[32 * 2304];            // [sentence | scene | speaker]
__device__ float  g_h_part[MLP_KC * 32 * 256];   // mlp1 partials [kc][b][j]
__device__ float  g_pp[3 * PROJ_KC * 32 * 512];  // proj partials [task][kc][b][j]
__device__ float2 g_nodes[32 * NODES];           // fused node table [b][m] (num,den)
__device__ float  g_frange[32 * 2];              // fused range [b][min,max]

__constant__ float CHEB[9] = {1.f, 0.92387953f, 0.70710678f, 0.38268343f, 0.f,
                              -0.38268343f, -0.70710678f, -0.92387953f, -1.f};
__constant__ float LAMB[9] = {0.5f, -1.f, 1.f, -1.f, 1.f, -1.f, 1.f, -1.f, 0.5f};

__device__ __forceinline__ float ex2f(float x) {
    float y; asm("ex2.approx.f32 %0, %1;" : "=f"(y) : "f"(x)); return y;
}
__device__ __forceinline__ float wredsum(float v) {
#pragma unroll
    for (int o = 16; o > 0; o >>= 1) v += __shfl_xor_sync(0xffffffffu, v, o);
    return v;
}

__device__ __forceinline__ float interp_s(float x, float xmin, float w, float hw,
                                          float invw,
                                          const float* __restrict__ snum,
                                          const float* __restrict__ sden) {
    int c = (int)((x - xmin) * invw);
    c = (c < 0) ? 0 : ((c >= NI) ? NI - 1 : c);
    const float x0 = xmin + (c + 0.5f) * w;
    const int base = c * NNODE;
    float wn = 0.f, wd = 0.f, hitn = 0.f, hitd = 1.f;
    bool hit = false;
#pragma unroll
    for (int m = 0; m < NNODE; m++) {
        float d = x - (x0 + hw * CHEB[m]);
        if (fabsf(d) < 1e-10f) { hit = true; hitn = snum[base + m]; hitd = sden[base + m]; d = 1.f; }
        float wm = __fdividef(LAMB[m], d);
        wn = fmaf(wm, snum[base + m], wn);
        wd = fmaf(wm, sden[base + m], wd);
    }
    return hit ? __fdividef(hitn, hitd) : __fdividef(wn, wd);
}

__device__ __forceinline__ float interp_g(float x, float xmin, float w, float hw,
                                          float invw,
                                          const float2* __restrict__ nodes) {
    int c = (int)((x - xmin) * invw);
    c = (c < 0) ? 0 : ((c >= NI) ? NI - 1 : c);
    const float x0 = xmin + (c + 0.5f) * w;
    const float2* nb = nodes + c * NNODE;
    float wn = 0.f, wd = 0.f, hitn = 0.f, hitd = 1.f;
    bool hit = false;
#pragma unroll
    for (int m = 0; m < NNODE; m++) {
        float2 nd = nb[m];
        float d = x - (x0 + hw * CHEB[m]);
        if (fabsf(d) < 1e-10f) { hit = true; hitn = nd.x; hitd = nd.y; d = 1.f; }
        float wm = __fdividef(LAMB[m], d);
        wn = fmaf(wm, nd.x, wn);
        wd = fmaf(wm, nd.y, wd);
    }
    return hit ? __fdividef(hitn, hitd) : __fdividef(wn, wd);
}

// ---------------------------------------------------------------------------
// Kernel 1 (R9-proven): two S=768 attentions via node eval + interpolation,
// + sentence copy. grid (32, 3), block 512.
// ---------------------------------------------------------------------------
__global__ void __launch_bounds__(512) attn_pre_interp(const float* __restrict__ sent,
                                                       const float* __restrict__ ts,
                                                       const float* __restrict__ oth,
                                                       const float* __restrict__ sd,
                                                       const float* __restrict__ ss) {
    const int b = blockIdx.x, task = blockIdx.y;
    const int tid = threadIdx.x, lane = tid & 31, wid = tid >> 5;

    if (task == 2) {
        for (int i = tid; i < 768; i += 512) g_fused[b * 2304 + i] = sent[b * 768 + i];
        return;
    }

    const float* q = (task == 0) ? oth : ss;
    const float* k = (task == 0) ? ts  : ss;
    const float* v = (task == 0) ? ts  : sd;
    const int outoff = (task == 0) ? 1536 : 768;

    __shared__ __align__(16) float sq[768], sk[768], sv[768];
    __shared__ float snum[NODES], sden[NODES];
    __shared__ float red[32];

    for (int i = tid; i < 768; i += 512) {
        sq[i] = q[b * 768 + i];
        sk[i] = k[b * 768 + i];
        sv[i] = v[b * 768 + i];
    }
    __syncthreads();

    float lmin = 1e30f, lmax = -1e30f;
    for (int i = tid; i < 768; i += 512) {
        float x = sq[i];
        lmin = fminf(lmin, x); lmax = fmaxf(lmax, x);
    }
#pragma unroll
    for (int o = 16; o > 0; o >>= 1) {
        lmin = fminf(lmin, __shfl_xor_sync(0xffffffffu, lmin, o));
        lmax = fmaxf(lmax, __shfl_xor_sync(0xffffffffu, lmax, o));
    }
    if (lane == 0) { red[wid] = lmin; red[16 + wid] = lmax; }
    __syncthreads();
    float xmin = red[0], xmax = red[16];
#pragma unroll
    for (int i = 1; i < 16; i++) { xmin = fminf(xmin, red[i]); xmax = fmaxf(xmax, red[16 + i]); }

    const float w  = (xmax - xmin) * (1.f / NI);
    const float hw = 0.5f * w;

    for (int m = wid; m < NODES; m += 16) {
        const int c = m / NNODE, mm = m - c * NNODE;
        const float Xl = (xmin + (c + 0.5f) * w + hw * CHEB[mm]) * LOG2E;
        float sn = 0.f, sd_ = 0.f;
        for (int t = lane; t < 768; t += 32) {
            float e = ex2f(Xl * sk[t]);
            sd_ += e;
            sn = fmaf(e, sv[t], sn);
        }
        sn = wredsum(sn); sd_ = wredsum(sd_);
        if (lane == 0) { snum[m] = sn; sden[m] = sd_; }
    }
    __syncthreads();

    const float invw = __fdividef(1.f, w);
    for (int s = tid; s < 768; s += 512)
        g_fused[b * 2304 + outoff + s] = interp_s(sq[s], xmin, w, hw, invw, snum, sden);
}

// ---------------------------------------------------------------------------
// Kernel 2 (R9-proven, fat): fused node table + shared projections.
// blocks [0,192): node eval; blocks [192,336): proj split-K.
// ---------------------------------------------------------------------------
__global__ void __launch_bounds__(256) fat_kernel(const float* __restrict__ sent,
                                                  const float* __restrict__ Wsh) {
    const int bx = blockIdx.x;
    const int tid = threadIdx.x, lane = tid & 31, wid = tid >> 5;

    if (bx < FAT_NODE_BLOCKS) {
        const int b = bx & 31, grp = bx >> 5;

        __shared__ __align__(16) float sf[2304];
        __shared__ float red[16];

        for (int i = tid; i < 576; i += 256)
            *reinterpret_cast<float4*>(sf + i * 4) =
                *reinterpret_cast<const float4*>(g_fused + b * 2304 + i * 4);
        __syncthreads();

        float lmin = 1e30f, lmax = -1e30f;
        for (int i = tid; i < 2304; i += 256) {
            float x = sf[i];
            lmin = fminf(lmin, x); lmax = fmaxf(lmax, x);
        }
#pragma unroll
        for (int o = 16; o > 0; o >>= 1) {
            lmin = fminf(lmin, __shfl_xor_sync(0xffffffffu, lmin, o));
            lmax = fmaxf(lmax, __shfl_xor_sync(0xffffffffu, lmax, o));
        }
        if (lane == 0) { red[wid] = lmin; red[8 + wid] = lmax; }
        __syncthreads();
        float xmin = red[0], xmax = red[8];
#pragma unroll
        for (int i = 1; i < 8; i++) { xmin = fminf(xmin, red[i]); xmax = fmaxf(xmax, red[8 + i]); }

        if (grp == 0 && tid == 0) { g_frange[b * 2] = xmin; g_frange[b * 2 + 1] = xmax; }

        const float w  = (xmax - xmin) * (1.f / NI);
        const float hw = 0.5f * w;
        const int m0 = grp * (NODES / NGRP);

        for (int m = m0 + wid; m < m0 + NODES / NGRP; m += 8) {
            const int c = m / NNODE, mm = m - c * NNODE;
            const float Xl = (xmin + (c + 0.5f) * w + hw * CHEB[mm]) * LOG2E;
            float sn = 0.f, sd_ = 0.f;
            for (int t = lane; t < 2304; t += 32) {
                float f = sf[t];
                float e = ex2f(Xl * f);
                sd_ += e;
                sn = fmaf(e, f, sn);     // v == f
            }
            sn = wredsum(sn); sd_ = wredsum(sd_);
            if (lane == 0) g_nodes[b * NODES + m] = make_float2(sn, sd_);
        }
        return;
    }

    // ----- proj section -----
    const int p    = bx - FAT_NODE_BLOCKS;
    const int task = p / (PROJ_KC * 2);
    const int rem  = p - task * PROJ_KC * 2;
    const int kc   = rem >> 1;
    const int jt   = rem & 1;
    const int j    = jt * 256 + tid;       // 0..511
    const int i0   = kc * PROJ_KCH;

    __shared__ __align__(16) float xs[PROJ_KCH][36];

    for (int e = tid; e < PROJ_KCH * 32; e += 256) {
        int i = e & 31, b = e >> 5;
        xs[i][b] = (task == 0) ? sent[b * 768 + i0 + i]
                               : g_fused[b * 2304 + 768 * task + i0 + i];
    }
    __syncthreads();

    float acc[32];
#pragma unroll
    for (int b = 0; b < 32; b++) acc[b] = 0.f;

#pragma unroll
    for (int i = 0; i < PROJ_KCH; i++) {
        float wv = Wsh[(i0 + i) * 512 + j];
#pragma unroll
        for (int b4 = 0; b4 < 8; b4++) {
            float4 x = *reinterpret_cast<const float4*>(&xs[i][b4 * 4]);
            acc[b4 * 4 + 0] = fmaf(x.x, wv, acc[b4 * 4 + 0]);
            acc[b4 * 4 + 1] = fmaf(x.y, wv, acc[b4 * 4 + 1]);
            acc[b4 * 4 + 2] = fmaf(x.z, wv, acc[b4 * 4 + 2]);
            acc[b4 * 4 + 3] = fmaf(x.w, wv, acc[b4 * 4 + 3]);
        }
    }

#pragma unroll
    for (int b = 0; b < 32; b++)
        g_pp[(((size_t)task * PROJ_KC + kc) * 32 + b) * 512 + j] = acc[b];
}

// ---------------------------------------------------------------------------
// Kernel 3 (R9-proven): mlp1 with fused assemble. grid MLP_KC (120), block 256.
// ---------------------------------------------------------------------------
__global__ void __launch_bounds__(256) mlp1_fused(const float* __restrict__ W1,
                                                  const float* __restrict__ bsh) {
    const int kc = blockIdx.x;
    const int i0 = kc * MLP_KCH;
    const int j  = threadIdx.x;

    __shared__ __align__(16) float xs[MLP_KCH][36];

    if (kc < 72) {
        for (int e = threadIdx.x; e < MLP_KCH * 32; e += 256) {
            int ii = e & 31, b = e >> 5;
            const float xmin = g_frange[b * 2], xmax = g_frange[b * 2 + 1];
            const float w  = (xmax - xmin) * (1.f / NI);
            const float hw = 0.5f * w;
            const float invw = __fdividef(1.f, w);
            const float x = g_fused[b * 2304 + i0 + ii];
            xs[ii][b] = interp_g(x, xmin, w, hw, invw, g_nodes + b * NODES);
        }
    } else {
        const int t0   = i0 - 2304;
        const int task = t0 >> 9;
        const int jj0  = t0 & 511;
        for (int e = threadIdx.x; e < MLP_KCH * 32; e += 256) {
            int jl = e & 31, b = e >> 5;
            const int jj = jj0 + jl;
            float a = bsh[jj];
            const float* pp = g_pp + (((size_t)task * PROJ_KC) * 32 + b) * 512 + jj;
#pragma unroll
            for (int s = 0; s < PROJ_KC; s++) a += pp[(size_t)s * 32 * 512];
            xs[jl][b] = a;
        }
    }
    __syncthreads();

    float acc[32];
#pragma unroll
    for (int b = 0; b < 32; b++) acc[b] = 0.f;

#pragma unroll
    for (int i = 0; i < MLP_KCH; i++) {
        float w = W1[(i0 + i) * 256 + j];
#pragma unroll
        for (int b4 = 0; b4 < 8; b4++) {
            float4 x = *reinterpret_cast<const float4*>(&xs[i][b4 * 4]);
            acc[b4 * 4 + 0] = fmaf(x.x, w, acc[b4 * 4 + 0]);
            acc[b4 * 4 + 1] = fmaf(x.y, w, acc[b4 * 4 + 1]);
            acc[b4 * 4 + 2] = fmaf(x.z, w, acc[b4 * 4 + 2]);
            acc[b4 * 4 + 3] = fmaf(x.w, w, acc[b4 * 4 + 3]);
        }
    }

#pragma unroll
    for (int b = 0; b < 32; b++)
        g_h_part[((size_t)kc * 32 + b) * 256 + j] = acc[b];
}

// ---------------------------------------------------------------------------
// Kernel 4 (NEW): tail with float4 16-way reduce.
// grid 32 (batch), block 1024 = 16 kc-groups x 64 float4-columns.
// Each thread sums 7-8 float4s (independent, coalesced), smem 16-way combine,
// float4 bias+relu, then 7-warp mlp2 + sigmoid.
// ---------------------------------------------------------------------------
__global__ void __launch_bounds__(1024) mlp_tail(const float* __restrict__ b1,
                                                 const float* __restrict__ W2,
                                                 const float* __restrict__ b2,
                                                 float* __restrict__ out) {
    const int b  = blockIdx.x;
    const int j4 = threadIdx.x & 63;          // float4 column 0..63
    const int qt = threadIdx.x >> 6;          // kc-group 0..15

    __shared__ __align__(16) float4 sred[16][64];
    __shared__ __align__(16) float h[256];

    // kc = qt + 16*s  (s = 0..7 for qt<8, s = 0..6 for qt>=8) covers 0..119
    const float4* src = reinterpret_cast<const float4*>(g_h_part);
    float4 a = make_float4(0.f, 0.f, 0.f, 0.f);
    const int ns = (qt < 8) ? 8 : 7;
#pragma unroll 8
    for (int s = 0; s < 8; s++) {
        if (s < ns) {
            const int kc = qt + 16 * s;
            float4 p = src[((size_t)kc * 32 + b) * 64 + j4];
            a.x += p.x; a.y += p.y; a.z += p.z; a.w += p.w;
        }
    }
    sred[qt][j4] = a;
    __syncthreads();

    if (threadIdx.x < 64) {
        float4 t = sred[0][threadIdx.x];
#pragma unroll
        for (int s = 1; s < 16; s++) {
            float4 p = sred[s][threadIdx.x];
            t.x += p.x; t.y += p.y; t.z += p.z; t.w += p.w;
        }
        float4 bb = reinterpret_cast<const float4*>(b1)[threadIdx.x];
        float4 hv;
        hv.x = fmaxf(t.x + bb.x, 0.f);
        hv.y = fmaxf(t.y + bb.y, 0.f);
        hv.z = fmaxf(t.z + bb.z, 0.f);
        hv.w = fmaxf(t.w + bb.w, 0.f);
        *reinterpret_cast<float4*>(h + threadIdx.x * 4) = hv;
    }
    __syncthreads();

    const int w = threadIdx.x >> 5, lane = threadIdx.x & 31;
    if (w < 7) {
        float s = 0.f;
#pragma unroll
        for (int q = 0; q < 8; q++)
            s = fmaf(h[q * 32 + lane], W2[(q * 32 + lane) * 7 + w], s);
#pragma unroll
        for (int o = 16; o > 0; o >>= 1) s += __shfl_xor_sync(0xffffffffu, s, o);
        if (lane == 0) out[b * 7 + w] = 1.f / (1.f + __expf(-(s + b2[w])));
    }
}

extern "C" void kernel_launch(void* const* d_in, const int* in_sizes, int n_in,
                              void* d_out, int out_size) {
    const float* sent = (const float*)d_in[0];
    const float* ts   = (const float*)d_in[1];
    const float* oth  = (const float*)d_in[2];
    const float* sd   = (const float*)d_in[3];
    const float* ss   = (const float*)d_in[4];
    const float* Wsh  = (const float*)d_in[5];
    const float* bsh  = (const float*)d_in[6];
    const float* W1   = (const float*)d_in[7];
    const float* b1   = (const float*)d_in[8];
    const float* W2   = (const float*)d_in[9];
    const float* b2   = (const float*)d_in[10];
    float* out = (float*)d_out;

    attn_pre_interp<<<dim3(32, 3), 512>>>(sent, ts, oth, sd, ss);
    fat_kernel<<<FAT_NODE_BLOCKS + FAT_PROJ_BLOCKS, 256>>>(sent, Wsh);
    mlp1_fused<<<MLP_KC, 256>>>(W1, bsh);
    mlp_tail<<<32, 1024>>>(b1, W2, b2, out);
}